// round 11
// baseline (speedup 1.0000x reference)
#include <cuda_runtime.h>
#include <cuda_fp16.h>
#include <cstdint>

// VQ layer via legacy mma.sync fp16 m16n8k16 (base sm_100 target).
//
// input (B=64, D=64, H=32, W=32) f32 ; codebook (K=1024, D=64) f32
// out f32: [idxes (65536)] [embed (4194304, layout (B,D,H,W))]
//
// d2 = ||c||^2 - 2 x.c ; fp16 2-split, f32 accumulate, error ~2^-22.
// R11: 64 regs/thread via __launch_bounds__(256,4) -> 4 CTAs/SM (32 warps,
// 8/SMSP). Latency hiding moves from ILP to TLP: bf single-buffered, B ring
// reduced to 2 buffers (52.5 KB smem/CTA).

#define NPTS    65536
#define DDIM    64
#define KCODES  1024
#define HWD     1024
#define NCHUNKS 16       // 16 x 64 codes
#define NTHREADS 256
#define MPTS    64       // points per CTA

// B fragments fp16: [chunk 0..15][ks 0..7][nt 0..7][lane 0..31] uint2
//   ks 0-3 = h1 cols, ks 4-7 = h2 cols.
__device__ uint2 g_Cf[NCHUNKS * 8 * 8 * 32];    // 256 KB (L2-resident)
__device__ float g_cnorm[KCODES];

// ---- dynamic smem (bytes) ----
#define SO_SCN   0                        // 1024 f32 cnorm
#define SO_MK    4096                     // 64 i32
#define SO_MB    4352                     // 64 f32
#define SO_A     4608                     // 16 KB A fp16 fragments
#define SO_B     20992                    // 2 x 16384 B ring; also raw staging
#define SMEM_TOTAL (SO_B + 2 * 16384)     // 53760 B -> 4 CTAs/SM

#define STAGE_STRIDE 68                   // floats per staged dim row (272 B)

// ---------------------------------------------------------------------------
__device__ __forceinline__ uint32_t smem_u32(const void* p) {
    uint32_t a;
    asm("{ .reg .u64 t; cvta.to.shared.u64 t, %1; cvt.u32.u64 %0, t; }"
        : "=r"(a) : "l"(p));
    return a;
}
__device__ __forceinline__ void cp_async16(uint32_t dst, const void* src) {
    asm volatile("cp.async.cg.shared.global [%0], [%1], 16;"
                 :: "r"(dst), "l"(src) : "memory");
}
#define CP_COMMIT() asm volatile("cp.async.commit_group;" ::: "memory")

__device__ __forceinline__ void lds128(uint32_t* r, uint32_t a) {
    asm volatile("ld.shared.v4.b32 {%0,%1,%2,%3}, [%4];"
                 : "=r"(r[0]), "=r"(r[1]), "=r"(r[2]), "=r"(r[3]) : "r"(a));
}
__device__ __forceinline__ void lds64(uint32_t* r, uint32_t a) {
    asm volatile("ld.shared.v2.b32 {%0,%1}, [%2];"
                 : "=r"(r[0]), "=r"(r[1]) : "r"(a));
}
__device__ __forceinline__ void lds64f(float* r, uint32_t a) {
    asm volatile("ld.shared.v2.f32 {%0,%1}, [%2];"
                 : "=f"(r[0]), "=f"(r[1]) : "r"(a));
}
__device__ __forceinline__ void sts128u(uint32_t a, uint32_t x, uint32_t y,
                                        uint32_t z, uint32_t w) {
    asm volatile("st.shared.v4.b32 [%0], {%1,%2,%3,%4};"
                 :: "r"(a), "r"(x), "r"(y), "r"(z), "r"(w) : "memory");
}
__device__ __forceinline__ void mma_f16(float* c, const uint32_t* a, const uint32_t* b) {
    asm volatile(
        "mma.sync.aligned.m16n8k16.row.col.f32.f16.f16.f32 "
        "{%0,%1,%2,%3}, {%4,%5,%6,%7}, {%8,%9}, {%0,%1,%2,%3};"
        : "+f"(c[0]), "+f"(c[1]), "+f"(c[2]), "+f"(c[3])
        : "r"(a[0]), "r"(a[1]), "r"(a[2]), "r"(a[3]), "r"(b[0]), "r"(b[1]));
}
__device__ __forceinline__ uint32_t packh2(__half lo, __half hi) {
    __half2 h = __halves2half2(lo, hi);
    return *reinterpret_cast<uint32_t*>(&h);
}
// value at concatenated column c (0-63: h1(dim c), 64-127: h2(dim c-64))
__device__ __forceinline__ __half split_h(float x, int c) {
    __half h1 = __float2half_rn(x);
    if (c < 64) return h1;
    return __float2half_rn(x - __half2float(h1));
}

// ---------------------------------------------------------------------------
// Prep: codebook -> g_Cf fp16 fragments + cnorm. 32 blocks of 32 codes.
// ---------------------------------------------------------------------------
__global__ __launch_bounds__(256) void prep_codebook(const float* __restrict__ cb) {
    __shared__ float sc[32][65];
    const int t = threadIdx.x;
    const int base = blockIdx.x * 32;
    const int c  = blockIdx.x >> 1;         // 64-code chunk
    const int qh = blockIdx.x & 1;          // nt half
#pragma unroll
    for (int it = 0; it < 8; it++) {
        int idx = it * 256 + t;
        int n = idx >> 6, d = idx & 63;
        sc[n][d] = cb[(size_t)(base + n) * DDIM + d];
    }
    __syncthreads();
    if (t < 32) {
        float s = 0.f;
#pragma unroll
        for (int d = 0; d < DDIM; d++) s = fmaf(sc[t][d], sc[t][d], s);
        g_cnorm[base + t] = s;
    }
#pragma unroll
    for (int it = 0; it < 4; it++) {
        int fi = it * 256 + t;
        int ks = fi >> 7, ntl = (fi >> 5) & 3, lane = fi & 31;
        int g = lane >> 2, tg = lane & 3;
        int nl = ntl * 8 + g;
        int c0 = ks * 16 + tg * 2;
        int d0 = c0 & 63;
        uint32_t b0 = packh2(split_h(sc[nl][d0],     c0),
                             split_h(sc[nl][d0 + 1], c0 + 1));
        uint32_t b1 = packh2(split_h(sc[nl][d0 + 8], c0 + 8),
                             split_h(sc[nl][d0 + 9], c0 + 9));
        g_Cf[(((size_t)c * 8 + ks) * 8 + (qh * 4 + ntl)) * 32 + lane] =
            make_uint2(b0, b1);
    }
}

// ---------------------------------------------------------------------------
// Main: 64 points x 1024 codes per CTA (1024 CTAs), 8 warps, 16x32 warp tile.
// ---------------------------------------------------------------------------
__global__ __launch_bounds__(NTHREADS, 4)
void vq_mma_kernel(const float* __restrict__ input,
                   const float* __restrict__ codebook,
                   float* __restrict__ out_idx,
                   float* __restrict__ out_embed) {
    extern __shared__ char smem[];
    const uint32_t sb = smem_u32(smem);
    const int tid  = threadIdx.x;
    const int wid  = tid >> 5;
    const int lane = tid & 31;
    const int g    = lane >> 2;
    const int tg   = lane & 3;
    const int wm   = wid & 3;      // mtile: rows [wm*16, wm*16+16)
    const int wn   = wid >> 2;     // cols [wn*32, wn*32+32) of 64-code chunk

    const int bm  = blockIdx.x;    // 1024 blocks
    const int b   = bm >> 4;
    const int hw0 = (bm & 15) * MPTS;

    // ---- G0: raw input tile (64 dims x 64 pts) -> B ring area, + cnorm ----
    {
        const float* src = input + (size_t)b * (DDIM * HWD) + hw0;
#pragma unroll
        for (int it = 0; it < 4; it++) {
            int idx = it * NTHREADS + tid;          // 1024 x 16B
            int row = idx >> 4, seg = idx & 15;
            cp_async16(sb + SO_B + (uint32_t)(row * (STAGE_STRIDE * 4) + seg * 16),
                       src + (size_t)row * HWD + seg * 4);
        }
        const float4* cn4 = reinterpret_cast<const float4*>(g_cnorm);
        cp_async16(sb + SO_SCN + tid * 16, cn4 + tid);
        CP_COMMIT();                            // G0
    }

    // ---- convert raw -> A fp16 fragments: 1024 entries [ks 0..7][mt 0..3] ----
    asm volatile("cp.async.wait_group 0;" ::: "memory");   // G0 done
    __syncthreads();
    {
        const float* stage = reinterpret_cast<const float*>(smem + SO_B);
#pragma unroll
        for (int it = 0; it < 4; it++) {
            int fi = it * NTHREADS + tid;
            int ks = fi >> 7, mt = (fi >> 5) & 3, ln = fi & 31;
            int gg = ln >> 2, t4 = ln & 3;
            int r0 = mt * 16 + gg, r1 = r0 + 8;
            int c0 = ks * 16 + t4 * 2;
            int d0 = c0 & 63;
            uint32_t a0 = packh2(split_h(stage[(d0)     * STAGE_STRIDE + r0], c0),
                                 split_h(stage[(d0 + 1) * STAGE_STRIDE + r0], c0 + 1));
            uint32_t a1 = packh2(split_h(stage[(d0)     * STAGE_STRIDE + r1], c0),
                                 split_h(stage[(d0 + 1) * STAGE_STRIDE + r1], c0 + 1));
            uint32_t a2 = packh2(split_h(stage[(d0 + 8) * STAGE_STRIDE + r0], c0 + 8),
                                 split_h(stage[(d0 + 9) * STAGE_STRIDE + r0], c0 + 9));
            uint32_t a3 = packh2(split_h(stage[(d0 + 8) * STAGE_STRIDE + r1], c0 + 8),
                                 split_h(stage[(d0 + 9) * STAGE_STRIDE + r1], c0 + 9));
            sts128u(sb + SO_A + fi * 16, a0, a1, a2, a3);
        }
    }
    __syncthreads();   // A ready; staging (B ring) dead

    // ---- ALL A fragments for this warp's mtile -> 32 registers ----
    uint32_t Ah1[4][4], Ah2[4][4];
#pragma unroll
    for (int k = 0; k < 4; k++) {
        lds128(Ah1[k], sb + SO_A + (uint32_t)(((k * 4 + wm) * 32 + lane) * 16));
        lds128(Ah2[k], sb + SO_A + (uint32_t)((((k + 4) * 4 + wm) * 32 + lane) * 16));
    }

    // ---- G1: chunk 0 -> buf 0 ; G2: chunk 1 -> buf 1 ----
    {
        const float4* Bsrc = reinterpret_cast<const float4*>(g_Cf);
#pragma unroll
        for (int it = 0; it < 4; it++) {
            int idx = it * NTHREADS + tid;
            cp_async16(sb + SO_B + idx * 16, Bsrc + idx);
        }
        CP_COMMIT();                            // G1
#pragma unroll
        for (int it = 0; it < 4; it++) {
            int idx = it * NTHREADS + tid;
            cp_async16(sb + SO_B + 16384 + idx * 16, Bsrc + 1024 + idx);
        }
        CP_COMMIT();                            // G2
    }

    float best[2];
    int   bestk[2];
#pragma unroll
    for (int i = 0; i < 2; i++) { best[i] = __int_as_float(0x7f7fffff); bestk[i] = 0; }

    const uint32_t bOffW = (uint32_t)((wn * 4 * 32 + lane) * 8);

    for (int ch = 0; ch < NCHUNKS; ch++) {
        if (ch < NCHUNKS - 1) asm volatile("cp.async.wait_group 1;" ::: "memory");
        else                  asm volatile("cp.async.wait_group 0;" ::: "memory");
        __syncthreads();   // chunk ch visible in buf ch&1

        const uint32_t bBase = sb + SO_B + (uint32_t)((ch & 1) * 16384) + bOffW;

        float acc[4][4];
#pragma unroll
        for (int nt = 0; nt < 4; nt++)
#pragma unroll
            for (int j = 0; j < 4; j++) acc[nt][j] = 0.f;

        // ksteps 0-3: B-h1 feeds (A-h1, A-h2); ksteps 4-7: B-h2 feeds A-h1.
        // bf single-buffered: 8 warps/SMSP provide the latency hiding.
#pragma unroll
        for (int k = 0; k < 8; k++) {
            uint32_t bf[4][2];
#pragma unroll
            for (int nt = 0; nt < 4; nt++)
                lds64(bf[nt], bBase + (uint32_t)((k * 8 + nt) * 256));
            if (k < 4) {
#pragma unroll
                for (int nt = 0; nt < 4; nt++) mma_f16(acc[nt], Ah1[k], bf[nt]);
#pragma unroll
                for (int nt = 0; nt < 4; nt++) mma_f16(acc[nt], Ah2[k], bf[nt]);
            } else {
#pragma unroll
                for (int nt = 0; nt < 4; nt++) mma_f16(acc[nt], Ah1[k - 4], bf[nt]);
            }
        }

        // ---- argmin fold (16 values/lane) ----
        {
            const int cb0 = ch * 64 + wn * 32;
#pragma unroll
            for (int nt = 0; nt < 4; nt++) {
                int col = cb0 + nt * 8 + tg * 2;
                float n2[2];
                lds64f(n2, sb + SO_SCN + (uint32_t)(col * 4));
#pragma unroll
                for (int hi = 0; hi < 2; hi++) {
                    float d0 = fmaf(-2.f, acc[nt][hi * 2 + 0], n2[0]);
                    float d1 = fmaf(-2.f, acc[nt][hi * 2 + 1], n2[1]);
                    if (d0 < best[hi]) { best[hi] = d0; bestk[hi] = col; }
                    if (d1 < best[hi]) { best[hi] = d1; bestk[hi] = col + 1; }
                }
            }
        }

        __syncthreads();   // buf ch&1 fully consumed before refill
        if (ch + 2 < NCHUNKS) {
            const float4* Bsrc = reinterpret_cast<const float4*>(g_Cf)
                                 + (size_t)(ch + 2) * 1024;
            const uint32_t bdst = sb + SO_B + (uint32_t)((ch & 1) * 16384);
#pragma unroll
            for (int it = 0; it < 4; it++) {
                int idx = it * NTHREADS + tid;
                cp_async16(bdst + idx * 16, Bsrc + idx);
            }
            CP_COMMIT();
        }
    }

    // ---- reduce 4 lanes (tg) sharing each row ----
#pragma unroll
    for (int i = 0; i < 2; i++) {
#pragma unroll
        for (int off = 1; off <= 2; off <<= 1) {
            float ob = __shfl_xor_sync(0xffffffffu, best[i], off);
            int   ok = __shfl_xor_sync(0xffffffffu, bestk[i], off);
            if (ob < best[i] || (ob == best[i] && ok < bestk[i])) {
                best[i] = ob; bestk[i] = ok;
            }
        }
    }

    // ---- merge the two warps (wn) sharing each row ----
    float* mb = reinterpret_cast<float*>(smem + SO_MB);
    int*   mk = reinterpret_cast<int*>(smem + SO_MK);
    if (wn == 0 && tg == 0) {
#pragma unroll
        for (int i = 0; i < 2; i++) {
            int r = wm * 16 + g + 8 * i;
            mb[r] = best[i]; mk[r] = bestk[i];
        }
    }
    __syncthreads();
    if (wn == 1 && tg == 0) {
#pragma unroll
        for (int i = 0; i < 2; i++) {
            int r = wm * 16 + g + 8 * i;
            float ob = mb[r]; int ok = mk[r];
            if (best[i] < ob || (best[i] == ob && bestk[i] < ok)) {
                mb[r] = best[i]; mk[r] = bestk[i];
            }
        }
    }
    __syncthreads();

    if (out_idx && tid < MPTS) out_idx[bm * MPTS + tid] = (float)mk[tid];

    // ---- embed gather: 256 threads, 16 channels each ----
    if (out_embed) {
        int p  = bm * MPTS + (tid & 63);
        int k  = mk[tid & 63];
        int bb = p >> 10, hw = p & 1023;
        int d0 = (tid >> 6) * 16;
        const float* crow = codebook + (size_t)k * DDIM + d0;
        float* op = out_embed + (size_t)bb * (DDIM * HWD) + (size_t)d0 * HWD + hw;
#pragma unroll
        for (int d = 0; d < 16; d++) op[(size_t)d * HWD] = __ldg(crow + d);
    }
}

// ---------------------------------------------------------------------------
extern "C" void kernel_launch(void* const* d_in, const int* in_sizes, int n_in,
                              void* d_out, int out_size) {
    const float* input    = (const float*)d_in[0];
    const float* codebook = (const float*)d_in[1];
    if (n_in >= 2 && in_sizes[0] == KCODES * DDIM && in_sizes[1] == NPTS * DDIM) {
        codebook = (const float*)d_in[0];
        input    = (const float*)d_in[1];
    }

    float* out = (float*)d_out;
    float* out_idx   = nullptr;
    float* out_embed = nullptr;
    if (out_size >= NPTS + NPTS * DDIM) {
        out_idx   = out;
        out_embed = out + NPTS;
    } else if (out_size == NPTS * DDIM) {
        out_embed = out;
    } else {
        out_idx = out;
    }

    cudaFuncSetAttribute(vq_mma_kernel,
                         cudaFuncAttributeMaxDynamicSharedMemorySize, SMEM_TOTAL);

    prep_codebook<<<32, 256>>>(codebook);
    vq_mma_kernel<<<NPTS / MPTS, NTHREADS, SMEM_TOTAL>>>(input, codebook,
                                                         out_idx, out_embed);
}

// round 12
// speedup vs baseline: 1.0227x; 1.0227x over previous
#include <cuda_runtime.h>
#include <cuda_fp16.h>
#include <cstdint>

// VQ layer via legacy mma.sync fp16 m16n8k16 (base sm_100 target).
//
// input (B=64, D=64, H=32, W=32) f32 ; codebook (K=1024, D=64) f32
// out f32: [idxes (65536)] [embed (4194304, layout (B,D,H,W))]
//
// d2 = ||c||^2 - 2 x.c ; fp16 2-split, f32 accumulate, error ~2^-22.
// R12: R10 config (64-pt CTAs, 3 CTAs/SM, triple-buffered B) + paired B
// fragment layout: adjacent nt fragments contiguous per lane, so one lds128
// replaces two lds64 (mainloop B-load instructions halved: 32 -> 16/chunk).

#define NPTS    65536
#define DDIM    64
#define KCODES  1024
#define HWD     1024
#define NCHUNKS 16       // 16 x 64 codes
#define NTHREADS 256
#define MPTS    64       // points per CTA

// B fragments fp16, PAIRED: [chunk][ks 0..7][ntp 0..3][lane] uint4 =
//   {b0(nt=2ntp), b1(nt=2ntp), b0(nt=2ntp+1), b1(nt=2ntp+1)}
//   ks 0-3 = h1 cols, ks 4-7 = h2 cols.
__device__ uint4 g_Cf[NCHUNKS * 8 * 4 * 32];    // 256 KB (L2-resident)
__device__ float g_cnorm[KCODES];

// ---- dynamic smem (bytes) ----
#define SO_SCN   0                        // 1024 f32 cnorm
#define SO_MK    4096                     // 64 i32
#define SO_MB    4352                     // 64 f32
#define SO_A     4608                     // 16 KB A fp16 fragments
#define SO_B     20992                    // 3 x 16384 B ring; also raw staging
#define SMEM_TOTAL (SO_B + 3 * 16384)     // 70144 B -> 3 CTAs/SM

#define STAGE_STRIDE 68                   // floats per staged dim row (272 B)

// ---------------------------------------------------------------------------
__device__ __forceinline__ uint32_t smem_u32(const void* p) {
    uint32_t a;
    asm("{ .reg .u64 t; cvta.to.shared.u64 t, %1; cvt.u32.u64 %0, t; }"
        : "=r"(a) : "l"(p));
    return a;
}
__device__ __forceinline__ void cp_async16(uint32_t dst, const void* src) {
    asm volatile("cp.async.cg.shared.global [%0], [%1], 16;"
                 :: "r"(dst), "l"(src) : "memory");
}
#define CP_COMMIT() asm volatile("cp.async.commit_group;" ::: "memory")

__device__ __forceinline__ void lds128(uint32_t* r, uint32_t a) {
    asm volatile("ld.shared.v4.b32 {%0,%1,%2,%3}, [%4];"
                 : "=r"(r[0]), "=r"(r[1]), "=r"(r[2]), "=r"(r[3]) : "r"(a));
}
__device__ __forceinline__ void lds64f(float* r, uint32_t a) {
    asm volatile("ld.shared.v2.f32 {%0,%1}, [%2];"
                 : "=f"(r[0]), "=f"(r[1]) : "r"(a));
}
__device__ __forceinline__ void sts128u(uint32_t a, uint32_t x, uint32_t y,
                                        uint32_t z, uint32_t w) {
    asm volatile("st.shared.v4.b32 [%0], {%1,%2,%3,%4};"
                 :: "r"(a), "r"(x), "r"(y), "r"(z), "r"(w) : "memory");
}
__device__ __forceinline__ void mma_f16(float* c, const uint32_t* a, const uint32_t* b) {
    asm volatile(
        "mma.sync.aligned.m16n8k16.row.col.f32.f16.f16.f32 "
        "{%0,%1,%2,%3}, {%4,%5,%6,%7}, {%8,%9}, {%0,%1,%2,%3};"
        : "+f"(c[0]), "+f"(c[1]), "+f"(c[2]), "+f"(c[3])
        : "r"(a[0]), "r"(a[1]), "r"(a[2]), "r"(a[3]), "r"(b[0]), "r"(b[1]));
}
__device__ __forceinline__ uint32_t packh2(__half lo, __half hi) {
    __half2 h = __halves2half2(lo, hi);
    return *reinterpret_cast<uint32_t*>(&h);
}
// value at concatenated column c (0-63: h1(dim c), 64-127: h2(dim c-64))
__device__ __forceinline__ __half split_h(float x, int c) {
    __half h1 = __float2half_rn(x);
    if (c < 64) return h1;
    return __float2half_rn(x - __half2float(h1));
}

// ---------------------------------------------------------------------------
// Prep: codebook -> g_Cf paired fp16 fragments + cnorm. 32 blocks of 32 codes.
// ---------------------------------------------------------------------------
__global__ __launch_bounds__(256) void prep_codebook(const float* __restrict__ cb) {
    __shared__ float sc[32][65];
    const int t = threadIdx.x;
    const int base = blockIdx.x * 32;
    const int c  = blockIdx.x >> 1;         // 64-code chunk
    const int qh = blockIdx.x & 1;          // ntp-half within chunk
#pragma unroll
    for (int it = 0; it < 8; it++) {
        int idx = it * 256 + t;
        int n = idx >> 6, d = idx & 63;
        sc[n][d] = cb[(size_t)(base + n) * DDIM + d];
    }
    __syncthreads();
    if (t < 32) {
        float s = 0.f;
#pragma unroll
        for (int d = 0; d < DDIM; d++) s = fmaf(sc[t][d], sc[t][d], s);
        g_cnorm[base + t] = s;
    }
    // 512 uint4 entries per block: [ks 0..7][ntpl 0..1][lane]
#pragma unroll
    for (int it = 0; it < 2; it++) {
        int fi = it * 256 + t;
        int ks = fi >> 6, ntpl = (fi >> 5) & 1, lane = fi & 31;
        int g = lane >> 2, tg = lane & 3;
        int c0 = ks * 16 + tg * 2;
        int d0 = c0 & 63;
        uint32_t fr[4];
#pragma unroll
        for (int p = 0; p < 2; p++) {
            int nl = (ntpl * 2 + p) * 8 + g;     // local code 0..31
            fr[p * 2 + 0] = packh2(split_h(sc[nl][d0],     c0),
                                   split_h(sc[nl][d0 + 1], c0 + 1));
            fr[p * 2 + 1] = packh2(split_h(sc[nl][d0 + 8], c0 + 8),
                                   split_h(sc[nl][d0 + 9], c0 + 9));
        }
        g_Cf[(((size_t)c * 8 + ks) * 4 + (qh * 2 + ntpl)) * 32 + lane] =
            make_uint4(fr[0], fr[1], fr[2], fr[3]);
    }
}

// ---------------------------------------------------------------------------
// Main: 64 points x 1024 codes per CTA (1024 CTAs), 8 warps, 16x32 warp tile.
// ---------------------------------------------------------------------------
__global__ __launch_bounds__(NTHREADS, 3)
void vq_mma_kernel(const float* __restrict__ input,
                   const float* __restrict__ codebook,
                   float* __restrict__ out_idx,
                   float* __restrict__ out_embed) {
    extern __shared__ char smem[];
    const uint32_t sb = smem_u32(smem);
    const int tid  = threadIdx.x;
    const int wid  = tid >> 5;
    const int lane = tid & 31;
    const int g    = lane >> 2;
    const int tg   = lane & 3;
    const int wm   = wid & 3;      // mtile: rows [wm*16, wm*16+16)
    const int wn   = wid >> 2;     // cols [wn*32, wn*32+32) of 64-code chunk

    const int bm  = blockIdx.x;    // 1024 blocks
    const int b   = bm >> 4;
    const int hw0 = (bm & 15) * MPTS;

    // ---- G0: raw input tile (64 dims x 64 pts) -> B ring area, + cnorm ----
    {
        const float* src = input + (size_t)b * (DDIM * HWD) + hw0;
#pragma unroll
        for (int it = 0; it < 4; it++) {
            int idx = it * NTHREADS + tid;          // 1024 x 16B
            int row = idx >> 4, seg = idx & 15;
            cp_async16(sb + SO_B + (uint32_t)(row * (STAGE_STRIDE * 4) + seg * 16),
                       src + (size_t)row * HWD + seg * 4);
        }
        const float4* cn4 = reinterpret_cast<const float4*>(g_cnorm);
        cp_async16(sb + SO_SCN + tid * 16, cn4 + tid);
        CP_COMMIT();                            // G0
    }
    // ---- G1: chunk 0 -> ring buf 2 (beyond 17.4 KB staging) ----
    {
        const float4* Bsrc = reinterpret_cast<const float4*>(g_Cf);
#pragma unroll
        for (int it = 0; it < 4; it++) {
            int idx = it * NTHREADS + tid;
            cp_async16(sb + SO_B + 2 * 16384 + idx * 16, Bsrc + idx);
        }
        CP_COMMIT();                            // G1
    }

    // ---- convert raw -> A fp16 fragments: 1024 entries [ks 0..7][mt 0..3] ----
    asm volatile("cp.async.wait_group 1;" ::: "memory");   // G0 done
    __syncthreads();
    {
        const float* stage = reinterpret_cast<const float*>(smem + SO_B);
#pragma unroll
        for (int it = 0; it < 4; it++) {
            int fi = it * NTHREADS + tid;
            int ks = fi >> 7, mt = (fi >> 5) & 3, ln = fi & 31;
            int gg = ln >> 2, t4 = ln & 3;
            int r0 = mt * 16 + gg, r1 = r0 + 8;
            int c0 = ks * 16 + t4 * 2;
            int d0 = c0 & 63;
            uint32_t a0 = packh2(split_h(stage[(d0)     * STAGE_STRIDE + r0], c0),
                                 split_h(stage[(d0 + 1) * STAGE_STRIDE + r0], c0 + 1));
            uint32_t a1 = packh2(split_h(stage[(d0)     * STAGE_STRIDE + r1], c0),
                                 split_h(stage[(d0 + 1) * STAGE_STRIDE + r1], c0 + 1));
            uint32_t a2 = packh2(split_h(stage[(d0 + 8) * STAGE_STRIDE + r0], c0 + 8),
                                 split_h(stage[(d0 + 9) * STAGE_STRIDE + r0], c0 + 9));
            uint32_t a3 = packh2(split_h(stage[(d0 + 8) * STAGE_STRIDE + r1], c0 + 8),
                                 split_h(stage[(d0 + 9) * STAGE_STRIDE + r1], c0 + 9));
            sts128u(sb + SO_A + fi * 16, a0, a1, a2, a3);
        }
    }
    __syncthreads();   // A ready; staging (bufs 0,1) dead

    // ---- ALL A fragments for this warp's mtile -> 32 registers ----
    uint32_t Ah1[4][4], Ah2[4][4];
#pragma unroll
    for (int k = 0; k < 4; k++) {
        lds128(Ah1[k], sb + SO_A + (uint32_t)(((k * 4 + wm) * 32 + lane) * 16));
        lds128(Ah2[k], sb + SO_A + (uint32_t)((((k + 4) * 4 + wm) * 32 + lane) * 16));
    }

    // ---- G2: chunk 1 -> ring buf 0 ; G3: chunk 2 -> ring buf 1 ----
    {
        const float4* Bsrc = reinterpret_cast<const float4*>(g_Cf);
#pragma unroll
        for (int it = 0; it < 4; it++) {
            int idx = it * NTHREADS + tid;
            cp_async16(sb + SO_B + idx * 16, Bsrc + 1024 + idx);
        }
        CP_COMMIT();                            // G2
#pragma unroll
        for (int it = 0; it < 4; it++) {
            int idx = it * NTHREADS + tid;
            cp_async16(sb + SO_B + 16384 + idx * 16, Bsrc + 2048 + idx);
        }
        CP_COMMIT();                            // G3
    }

    float best[2];
    int   bestk[2];
#pragma unroll
    for (int i = 0; i < 2; i++) { best[i] = __int_as_float(0x7f7fffff); bestk[i] = 0; }

    // warp's B base: ntp = wn*2 + j ; addr = ((ks*4 + ntp)*32 + lane)*16
    const uint32_t bOffW = (uint32_t)((wn * 2 * 32 + lane) * 16);

    for (int ch = 0; ch < NCHUNKS; ch++) {
        if (ch < NCHUNKS - 1) asm volatile("cp.async.wait_group 1;" ::: "memory");
        else                  asm volatile("cp.async.wait_group 0;" ::: "memory");
        __syncthreads();   // chunk ch visible; all warps done with ch-1

        // refill: chunk ch+2 -> buf (ch+1)%3 (consumed at chunk ch-1)
        if (ch >= 1 && ch + 2 < NCHUNKS) {
            const float4* Bsrc = reinterpret_cast<const float4*>(g_Cf)
                                 + (size_t)(ch + 2) * 1024;
            const uint32_t bdst = sb + SO_B + (uint32_t)(((ch + 1) % 3) * 16384);
#pragma unroll
            for (int it = 0; it < 4; it++) {
                int idx = it * NTHREADS + tid;
                cp_async16(bdst + idx * 16, Bsrc + idx);
            }
            CP_COMMIT();
        }

        const uint32_t bBase = sb + SO_B + (uint32_t)(((ch + 2) % 3) * 16384) + bOffW;

        float acc[4][4];
#pragma unroll
        for (int nt = 0; nt < 4; nt++)
#pragma unroll
            for (int j = 0; j < 4; j++) acc[nt][j] = 0.f;

        // paired B loads: 2 lds128/kstep = 4 fragments; double-buffered
        uint32_t bq[2][2][4];   // [buf][j][4] ; fragment nt: &bq[buf][nt>>1][(nt&1)*2]
#pragma unroll
        for (int j = 0; j < 2; j++)
            lds128(bq[0][j], bBase + (uint32_t)(j * 512));

        // ksteps 0-3: B-h1 feeds (A-h1, A-h2); ksteps 4-7: B-h2 feeds A-h1
#pragma unroll
        for (int k = 0; k < 8; k++) {
            const int cur = k & 1, nxt = cur ^ 1;
            if (k < 7) {
#pragma unroll
                for (int j = 0; j < 2; j++)
                    lds128(bq[nxt][j], bBase + (uint32_t)((k + 1) * 2048 + j * 512));
            }
            if (k < 4) {
#pragma unroll
                for (int nt = 0; nt < 4; nt++)
                    mma_f16(acc[nt], Ah1[k], &bq[cur][nt >> 1][(nt & 1) * 2]);
#pragma unroll
                for (int nt = 0; nt < 4; nt++)
                    mma_f16(acc[nt], Ah2[k], &bq[cur][nt >> 1][(nt & 1) * 2]);
            } else {
#pragma unroll
                for (int nt = 0; nt < 4; nt++)
                    mma_f16(acc[nt], Ah1[k - 4], &bq[cur][nt >> 1][(nt & 1) * 2]);
            }
        }

        // ---- argmin fold (16 values/lane) ----
        {
            const int cb0 = ch * 64 + wn * 32;
#pragma unroll
            for (int nt = 0; nt < 4; nt++) {
                int col = cb0 + nt * 8 + tg * 2;
                float n2[2];
                lds64f(n2, sb + SO_SCN + (uint32_t)(col * 4));
#pragma unroll
                for (int hi = 0; hi < 2; hi++) {
                    float d0 = fmaf(-2.f, acc[nt][hi * 2 + 0], n2[0]);
                    float d1 = fmaf(-2.f, acc[nt][hi * 2 + 1], n2[1]);
                    if (d0 < best[hi]) { best[hi] = d0; bestk[hi] = col; }
                    if (d1 < best[hi]) { best[hi] = d1; bestk[hi] = col + 1; }
                }
            }
        }
        // no trailing barrier — next iteration's top barrier protects refill
    }

    // ---- reduce 4 lanes (tg) sharing each row ----
#pragma unroll
    for (int i = 0; i < 2; i++) {
#pragma unroll
        for (int off = 1; off <= 2; off <<= 1) {
            float ob = __shfl_xor_sync(0xffffffffu, best[i], off);
            int   ok = __shfl_xor_sync(0xffffffffu, bestk[i], off);
            if (ob < best[i] || (ob == best[i] && ok < bestk[i])) {
                best[i] = ob; bestk[i] = ok;
            }
        }
    }

    // ---- merge the two warps (wn) sharing each row ----
    float* mb = reinterpret_cast<float*>(smem + SO_MB);
    int*   mk = reinterpret_cast<int*>(smem + SO_MK);
    if (wn == 0 && tg == 0) {
#pragma unroll
        for (int i = 0; i < 2; i++) {
            int r = wm * 16 + g + 8 * i;
            mb[r] = best[i]; mk[r] = bestk[i];
        }
    }
    __syncthreads();
    if (wn == 1 && tg == 0) {
#pragma unroll
        for (int i = 0; i < 2; i++) {
            int r = wm * 16 + g + 8 * i;
            float ob = mb[r]; int ok = mk[r];
            if (best[i] < ob || (best[i] == ob && bestk[i] < ok)) {
                mb[r] = best[i]; mk[r] = bestk[i];
            }
        }
    }
    __syncthreads();

    if (out_idx && tid < MPTS) out_idx[bm * MPTS + tid] = (float)mk[tid];

    // ---- embed gather: 256 threads, 16 channels each ----
    if (out_embed) {
        int p  = bm * MPTS + (tid & 63);
        int k  = mk[tid & 63];
        int bb = p >> 10, hw = p & 1023;
        int d0 = (tid >> 6) * 16;
        const float* crow = codebook + (size_t)k * DDIM + d0;
        float* op = out_embed + (size_t)bb * (DDIM * HWD) + (size_t)d0 * HWD + hw;
#pragma unroll
        for (int d = 0; d < 16; d++) op[(size_t)d * HWD] = __ldg(crow + d);
    }
}

// ---------------------------------------------------------------------------
extern "C" void kernel_launch(void* const* d_in, const int* in_sizes, int n_in,
                              void* d_out, int out_size) {
    const float* input    = (const float*)d_in[0];
    const float* codebook = (const float*)d_in[1];
    if (n_in >= 2 && in_sizes[0] == KCODES * DDIM && in_sizes[1] == NPTS * DDIM) {
        codebook = (const float*)d_in[0];
        input    = (const float*)d_in[1];
    }

    float* out = (float*)d_out;
    float* out_idx   = nullptr;
    float* out_embed = nullptr;
    if (out_size >= NPTS + NPTS * DDIM) {
        out_idx   = out;
        out_embed = out + NPTS;
    } else if (out_size == NPTS * DDIM) {
        out_embed = out;
    } else {
        out_idx = out;
    }

    cudaFuncSetAttribute(vq_mma_kernel,
                         cudaFuncAttributeMaxDynamicSharedMemorySize, SMEM_TOTAL);

    prep_codebook<<<32, 256>>>(codebook);
    vq_mma_kernel<<<NPTS / MPTS, NTHREADS, SMEM_TOTAL>>>(input, codebook,
                                                         out_idx, out_embed);
}

// round 13
// speedup vs baseline: 1.0408x; 1.0177x over previous
#include <cuda_runtime.h>
#include <cuda_fp16.h>
#include <cstdint>

// VQ layer via legacy mma.sync fp16 m16n8k16 (base sm_100 target).
//
// input (B=64, D=64, H=32, W=32) f32 ; codebook (K=1024, D=64) f32
// out f32: [idxes (65536)] [embed (4194304, layout (B,D,H,W))]
//
// d2 = ||c||^2 - 2 x.c ; fp16 2-split, f32 accumulate, error ~2^-22.
// R13: persistent work-stealing CTAs — grid = 148*3 = 444 workers, tiles of
// 64 points claimed via atomic counter (reset each launch by prep kernel).
// Removes the 3-vs-2.33 CTA-slot quantization tail of the 1024-CTA launch.
// Mainloop identical to R12 (paired B fragments, triple-buffered ring).

#define NPTS    65536
#define DDIM    64
#define KCODES  1024
#define HWD     1024
#define NCHUNKS 16       // 16 x 64 codes
#define NTHREADS 256
#define MPTS    64       // points per tile
#define NTILES  (NPTS / MPTS)   // 1024
#define NWORKERS 444            // 148 SMs x 3 CTAs

// B fragments fp16, PAIRED: [chunk][ks 0..7][ntp 0..3][lane] uint4
//   ks 0-3 = h1 cols, ks 4-7 = h2 cols.
__device__ uint4 g_Cf[NCHUNKS * 8 * 4 * 32];    // 256 KB (L2-resident)
__device__ float g_cnorm[KCODES];
__device__ int   g_tile_ctr;

// ---- dynamic smem (bytes) ----
#define SO_SCN   0                        // 1024 f32 cnorm
#define SO_MK    4096                     // 64 i32 merge k ; mk[0] reused for bm bcast
#define SO_MB    4352                     // 64 f32
#define SO_A     4608                     // 16 KB A fp16 fragments
#define SO_B     20992                    // 3 x 16384 B ring; also raw staging
#define SMEM_TOTAL (SO_B + 3 * 16384)     // 70144 B -> 3 CTAs/SM

#define STAGE_STRIDE 68                   // floats per staged dim row (272 B)

// ---------------------------------------------------------------------------
__device__ __forceinline__ uint32_t smem_u32(const void* p) {
    uint32_t a;
    asm("{ .reg .u64 t; cvta.to.shared.u64 t, %1; cvt.u32.u64 %0, t; }"
        : "=r"(a) : "l"(p));
    return a;
}
__device__ __forceinline__ void cp_async16(uint32_t dst, const void* src) {
    asm volatile("cp.async.cg.shared.global [%0], [%1], 16;"
                 :: "r"(dst), "l"(src) : "memory");
}
#define CP_COMMIT() asm volatile("cp.async.commit_group;" ::: "memory")

__device__ __forceinline__ void lds128(uint32_t* r, uint32_t a) {
    asm volatile("ld.shared.v4.b32 {%0,%1,%2,%3}, [%4];"
                 : "=r"(r[0]), "=r"(r[1]), "=r"(r[2]), "=r"(r[3]) : "r"(a));
}
__device__ __forceinline__ void lds64f(float* r, uint32_t a) {
    asm volatile("ld.shared.v2.f32 {%0,%1}, [%2];"
                 : "=f"(r[0]), "=f"(r[1]) : "r"(a));
}
__device__ __forceinline__ void sts128u(uint32_t a, uint32_t x, uint32_t y,
                                        uint32_t z, uint32_t w) {
    asm volatile("st.shared.v4.b32 [%0], {%1,%2,%3,%4};"
                 :: "r"(a), "r"(x), "r"(y), "r"(z), "r"(w) : "memory");
}
__device__ __forceinline__ void mma_f16(float* c, const uint32_t* a, const uint32_t* b) {
    asm volatile(
        "mma.sync.aligned.m16n8k16.row.col.f32.f16.f16.f32 "
        "{%0,%1,%2,%3}, {%4,%5,%6,%7}, {%8,%9}, {%0,%1,%2,%3};"
        : "+f"(c[0]), "+f"(c[1]), "+f"(c[2]), "+f"(c[3])
        : "r"(a[0]), "r"(a[1]), "r"(a[2]), "r"(a[3]), "r"(b[0]), "r"(b[1]));
}
__device__ __forceinline__ uint32_t packh2(__half lo, __half hi) {
    __half2 h = __halves2half2(lo, hi);
    return *reinterpret_cast<uint32_t*>(&h);
}
// value at concatenated column c (0-63: h1(dim c), 64-127: h2(dim c-64))
__device__ __forceinline__ __half split_h(float x, int c) {
    __half h1 = __float2half_rn(x);
    if (c < 64) return h1;
    return __float2half_rn(x - __half2float(h1));
}

// ---------------------------------------------------------------------------
// Prep: codebook -> g_Cf paired fp16 fragments + cnorm; reset tile counter.
// ---------------------------------------------------------------------------
__global__ __launch_bounds__(256) void prep_codebook(const float* __restrict__ cb) {
    __shared__ float sc[32][65];
    const int t = threadIdx.x;
    if (blockIdx.x == 0 && t == 0) g_tile_ctr = NWORKERS;   // reset each launch
    const int base = blockIdx.x * 32;
    const int c  = blockIdx.x >> 1;         // 64-code chunk
    const int qh = blockIdx.x & 1;          // ntp-half within chunk
#pragma unroll
    for (int it = 0; it < 8; it++) {
        int idx = it * 256 + t;
        int n = idx >> 6, d = idx & 63;
        sc[n][d] = cb[(size_t)(base + n) * DDIM + d];
    }
    __syncthreads();
    if (t < 32) {
        float s = 0.f;
#pragma unroll
        for (int d = 0; d < DDIM; d++) s = fmaf(sc[t][d], sc[t][d], s);
        g_cnorm[base + t] = s;
    }
#pragma unroll
    for (int it = 0; it < 2; it++) {
        int fi = it * 256 + t;
        int ks = fi >> 6, ntpl = (fi >> 5) & 1, lane = fi & 31;
        int g = lane >> 2, tg = lane & 3;
        int c0 = ks * 16 + tg * 2;
        int d0 = c0 & 63;
        uint32_t fr[4];
#pragma unroll
        for (int p = 0; p < 2; p++) {
            int nl = (ntpl * 2 + p) * 8 + g;
            fr[p * 2 + 0] = packh2(split_h(sc[nl][d0],     c0),
                                   split_h(sc[nl][d0 + 1], c0 + 1));
            fr[p * 2 + 1] = packh2(split_h(sc[nl][d0 + 8], c0 + 8),
                                   split_h(sc[nl][d0 + 9], c0 + 9));
        }
        g_Cf[(((size_t)c * 8 + ks) * 4 + (qh * 2 + ntpl)) * 32 + lane] =
            make_uint4(fr[0], fr[1], fr[2], fr[3]);
    }
}

// ---------------------------------------------------------------------------
// Main: persistent workers; each iteration = 64 points x 1024 codes.
// ---------------------------------------------------------------------------
__global__ __launch_bounds__(NTHREADS, 3)
void vq_mma_kernel(const float* __restrict__ input,
                   const float* __restrict__ codebook,
                   float* __restrict__ out_idx,
                   float* __restrict__ out_embed) {
    extern __shared__ char smem[];
    const uint32_t sb = smem_u32(smem);
    const int tid  = threadIdx.x;
    const int wid  = tid >> 5;
    const int lane = tid & 31;
    const int g    = lane >> 2;
    const int tg   = lane & 3;
    const int wm   = wid & 3;      // mtile: rows [wm*16, wm*16+16)
    const int wn   = wid >> 2;     // cols [wn*32, wn*32+32) of 64-code chunk

    float* mb = reinterpret_cast<float*>(smem + SO_MB);
    int*   mk = reinterpret_cast<int*>(smem + SO_MK);

    // cnorm -> smem once per worker (joins first tile's G0 commit group)
    {
        const float4* cn4 = reinterpret_cast<const float4*>(g_cnorm);
        cp_async16(sb + SO_SCN + tid * 16, cn4 + tid);
    }

    const uint32_t bOffW = (uint32_t)((wn * 2 * 32 + lane) * 16);

    int bm = blockIdx.x;
    while (bm < NTILES) {
        const int b   = bm >> 4;
        const int hw0 = (bm & 15) * MPTS;

        // ---- G0: raw input tile (64 dims x 64 pts) -> ring bufs 0/1 area ----
        {
            const float* src = input + (size_t)b * (DDIM * HWD) + hw0;
#pragma unroll
            for (int it = 0; it < 4; it++) {
                int idx = it * NTHREADS + tid;          // 1024 x 16B
                int row = idx >> 4, seg = idx & 15;
                cp_async16(sb + SO_B + (uint32_t)(row * (STAGE_STRIDE * 4) + seg * 16),
                           src + (size_t)row * HWD + seg * 4);
            }
            CP_COMMIT();                            // G0 (+cnorm on 1st tile)
        }
        // ---- G1: chunk 0 -> ring buf 2 (beyond 17.4 KB staging) ----
        {
            const float4* Bsrc = reinterpret_cast<const float4*>(g_Cf);
#pragma unroll
            for (int it = 0; it < 4; it++) {
                int idx = it * NTHREADS + tid;
                cp_async16(sb + SO_B + 2 * 16384 + idx * 16, Bsrc + idx);
            }
            CP_COMMIT();                            // G1
        }

        // ---- convert raw -> A fp16 fragments: [ks 0..7][mt 0..3][lane] ----
        asm volatile("cp.async.wait_group 1;" ::: "memory");   // G0 done
        __syncthreads();
        {
            const float* stage = reinterpret_cast<const float*>(smem + SO_B);
#pragma unroll
            for (int it = 0; it < 4; it++) {
                int fi = it * NTHREADS + tid;
                int ks = fi >> 7, mt = (fi >> 5) & 3, ln = fi & 31;
                int gg = ln >> 2, t4 = ln & 3;
                int r0 = mt * 16 + gg, r1 = r0 + 8;
                int c0 = ks * 16 + t4 * 2;
                int d0 = c0 & 63;
                uint32_t a0 = packh2(split_h(stage[(d0)     * STAGE_STRIDE + r0], c0),
                                     split_h(stage[(d0 + 1) * STAGE_STRIDE + r0], c0 + 1));
                uint32_t a1 = packh2(split_h(stage[(d0)     * STAGE_STRIDE + r1], c0),
                                     split_h(stage[(d0 + 1) * STAGE_STRIDE + r1], c0 + 1));
                uint32_t a2 = packh2(split_h(stage[(d0 + 8) * STAGE_STRIDE + r0], c0 + 8),
                                     split_h(stage[(d0 + 9) * STAGE_STRIDE + r0], c0 + 9));
                uint32_t a3 = packh2(split_h(stage[(d0 + 8) * STAGE_STRIDE + r1], c0 + 8),
                                     split_h(stage[(d0 + 9) * STAGE_STRIDE + r1], c0 + 9));
                sts128u(sb + SO_A + fi * 16, a0, a1, a2, a3);
            }
        }
        __syncthreads();   // A ready; staging (bufs 0,1) dead

        // ---- ALL A fragments for this warp's mtile -> 32 registers ----
        uint32_t Ah1[4][4], Ah2[4][4];
#pragma unroll
        for (int k = 0; k < 4; k++) {
            lds128(Ah1[k], sb + SO_A + (uint32_t)(((k * 4 + wm) * 32 + lane) * 16));
            lds128(Ah2[k], sb + SO_A + (uint32_t)((((k + 4) * 4 + wm) * 32 + lane) * 16));
        }

        // ---- G2: chunk 1 -> ring buf 0 ; G3: chunk 2 -> ring buf 1 ----
        {
            const float4* Bsrc = reinterpret_cast<const float4*>(g_Cf);
#pragma unroll
            for (int it = 0; it < 4; it++) {
                int idx = it * NTHREADS + tid;
                cp_async16(sb + SO_B + idx * 16, Bsrc + 1024 + idx);
            }
            CP_COMMIT();                            // G2
#pragma unroll
            for (int it = 0; it < 4; it++) {
                int idx = it * NTHREADS + tid;
                cp_async16(sb + SO_B + 16384 + idx * 16, Bsrc + 2048 + idx);
            }
            CP_COMMIT();                            // G3
        }

        float best[2];
        int   bestk[2];
#pragma unroll
        for (int i = 0; i < 2; i++) { best[i] = __int_as_float(0x7f7fffff); bestk[i] = 0; }

        for (int ch = 0; ch < NCHUNKS; ch++) {
            if (ch < NCHUNKS - 1) asm volatile("cp.async.wait_group 1;" ::: "memory");
            else                  asm volatile("cp.async.wait_group 0;" ::: "memory");
            __syncthreads();   // chunk ch visible; all warps done with ch-1

            // refill: chunk ch+2 -> buf (ch+1)%3 (consumed at chunk ch-1)
            if (ch >= 1 && ch + 2 < NCHUNKS) {
                const float4* Bsrc = reinterpret_cast<const float4*>(g_Cf)
                                     + (size_t)(ch + 2) * 1024;
                const uint32_t bdst = sb + SO_B + (uint32_t)(((ch + 1) % 3) * 16384);
#pragma unroll
                for (int it = 0; it < 4; it++) {
                    int idx = it * NTHREADS + tid;
                    cp_async16(bdst + idx * 16, Bsrc + idx);
                }
                CP_COMMIT();
            }

            const uint32_t bBase = sb + SO_B + (uint32_t)(((ch + 2) % 3) * 16384) + bOffW;

            float acc[4][4];
#pragma unroll
            for (int nt = 0; nt < 4; nt++)
#pragma unroll
                for (int j = 0; j < 4; j++) acc[nt][j] = 0.f;

            uint32_t bq[2][2][4];
#pragma unroll
            for (int j = 0; j < 2; j++)
                lds128(bq[0][j], bBase + (uint32_t)(j * 512));

#pragma unroll
            for (int k = 0; k < 8; k++) {
                const int cur = k & 1, nxt = cur ^ 1;
                if (k < 7) {
#pragma unroll
                    for (int j = 0; j < 2; j++)
                        lds128(bq[nxt][j], bBase + (uint32_t)((k + 1) * 2048 + j * 512));
                }
                if (k < 4) {
#pragma unroll
                    for (int nt = 0; nt < 4; nt++)
                        mma_f16(acc[nt], Ah1[k], &bq[cur][nt >> 1][(nt & 1) * 2]);
#pragma unroll
                    for (int nt = 0; nt < 4; nt++)
                        mma_f16(acc[nt], Ah2[k], &bq[cur][nt >> 1][(nt & 1) * 2]);
                } else {
#pragma unroll
                    for (int nt = 0; nt < 4; nt++)
                        mma_f16(acc[nt], Ah1[k - 4], &bq[cur][nt >> 1][(nt & 1) * 2]);
                }
            }

            // ---- argmin fold (16 values/lane) ----
            {
                const int cb0 = ch * 64 + wn * 32;
#pragma unroll
                for (int nt = 0; nt < 4; nt++) {
                    int col = cb0 + nt * 8 + tg * 2;
                    float n2[2];
                    lds64f(n2, sb + SO_SCN + (uint32_t)(col * 4));
#pragma unroll
                    for (int hi = 0; hi < 2; hi++) {
                        float d0 = fmaf(-2.f, acc[nt][hi * 2 + 0], n2[0]);
                        float d1 = fmaf(-2.f, acc[nt][hi * 2 + 1], n2[1]);
                        if (d0 < best[hi]) { best[hi] = d0; bestk[hi] = col; }
                        if (d1 < best[hi]) { best[hi] = d1; bestk[hi] = col + 1; }
                    }
                }
            }
        }

        // ---- reduce 4 lanes (tg) sharing each row ----
#pragma unroll
        for (int i = 0; i < 2; i++) {
#pragma unroll
            for (int off = 1; off <= 2; off <<= 1) {
                float ob = __shfl_xor_sync(0xffffffffu, best[i], off);
                int   ok = __shfl_xor_sync(0xffffffffu, bestk[i], off);
                if (ob < best[i] || (ob == best[i] && ok < bestk[i])) {
                    best[i] = ob; bestk[i] = ok;
                }
            }
        }

        // ---- merge the two warps (wn) sharing each row ----
        if (wn == 0 && tg == 0) {
#pragma unroll
            for (int i = 0; i < 2; i++) {
                int r = wm * 16 + g + 8 * i;
                mb[r] = best[i]; mk[r] = bestk[i];
            }
        }
        __syncthreads();
        if (wn == 1 && tg == 0) {
#pragma unroll
            for (int i = 0; i < 2; i++) {
                int r = wm * 16 + g + 8 * i;
                float ob = mb[r]; int ok = mk[r];
                if (best[i] < ob || (best[i] == ob && bestk[i] < ok)) {
                    mb[r] = best[i]; mk[r] = bestk[i];
                }
            }
        }
        __syncthreads();

        if (out_idx && tid < MPTS) out_idx[bm * MPTS + tid] = (float)mk[tid];

        // ---- embed gather: 256 threads, 16 channels each ----
        if (out_embed) {
            int p  = bm * MPTS + (tid & 63);
            int k  = mk[tid & 63];
            int bb = p >> 10, hw = p & 1023;
            int d0 = (tid >> 6) * 16;
            const float* crow = codebook + (size_t)k * DDIM + d0;
            float* op = out_embed + (size_t)bb * (DDIM * HWD) + (size_t)d0 * HWD + hw;
#pragma unroll
            for (int d = 0; d < 16; d++) op[(size_t)d * HWD] = __ldg(crow + d);
        }

        // ---- claim next tile (gather must finish reading mk first) ----
        __syncthreads();
        if (tid == 0) mk[0] = atomicAdd(&g_tile_ctr, 1);
        __syncthreads();
        bm = mk[0];
        // loop-top staging writes don't touch SO_MK/SO_SCN; ring reuse is
        // safe because all cp.async groups drained (wait_group 0 at ch 15)
        // and the syncthreads above orders all LDS before new STS.
    }
}

// ---------------------------------------------------------------------------
extern "C" void kernel_launch(void* const* d_in, const int* in_sizes, int n_in,
                              void* d_out, int out_size) {
    const float* input    = (const float*)d_in[0];
    const float* codebook = (const float*)d_in[1];
    if (n_in >= 2 && in_sizes[0] == KCODES * DDIM && in_sizes[1] == NPTS * DDIM) {
        codebook = (const float*)d_in[0];
        input    = (const float*)d_in[1];
    }

    float* out = (float*)d_out;
    float* out_idx   = nullptr;
    float* out_embed = nullptr;
    if (out_size >= NPTS + NPTS * DDIM) {
        out_idx   = out;
        out_embed = out + NPTS;
    } else if (out_size == NPTS * DDIM) {
        out_embed = out;
    } else {
        out_idx = out;
    }

    cudaFuncSetAttribute(vq_mma_kernel,
                         cudaFuncAttributeMaxDynamicSharedMemorySize, SMEM_TOTAL);

    prep_codebook<<<32, 256>>>(codebook);
    vq_mma_kernel<<<NWORKERS, NTHREADS, SMEM_TOTAL>>>(input, codebook,
                                                      out_idx, out_embed);
}